// round 4
// baseline (speedup 1.0000x reference)
#include <cuda_runtime.h>
#include <math_constants.h>

#define N_BATCH 128
#define W_IN    128
#define W_UP    1024
#define STEP_F  (127.0f / 1023.0f)

// Accumulators: [0] = sum of (min-dist * mask) over BOTH directions,
//               [1] = sum of index-order penalties over BOTH directions,
//               [2] = sum of direct squared error * mask.
__device__ float g_acc[3];

__global__ void zero_kernel() {
    if (threadIdx.x < 3) g_acc[threadIdx.x] = 0.0f;
}

// Min + first-occurrence argmin of squared distance from (x,y) to arr[0..1023].
// 4 independent accumulators break the loop-carried dependence; merge is exact
// (smallest index among bitwise-equal minima), matching jnp.argmin semantics.
__device__ __forceinline__ void min_scan(float x, float y,
                                         const float2* __restrict__ arr,
                                         float& best_out, int& idx_out) {
    float b0 = CUDART_INF_F, b1 = CUDART_INF_F, b2 = CUDART_INF_F, b3 = CUDART_INF_F;
    int j0 = 0, j1 = 1, j2 = 2, j3 = 3;
    #pragma unroll 2
    for (int j = 0; j < W_UP; j += 4) {
        float2 a0 = arr[j + 0];
        float2 a1 = arr[j + 1];
        float2 a2 = arr[j + 2];
        float2 a3 = arr[j + 3];
        float dx0 = x - a0.x, dy0 = y - a0.y;
        float d0 = dx0 * dx0 + dy0 * dy0;
        float dx1 = x - a1.x, dy1 = y - a1.y;
        float d1 = dx1 * dx1 + dy1 * dy1;
        float dx2 = x - a2.x, dy2 = y - a2.y;
        float d2 = dx2 * dx2 + dy2 * dy2;
        float dx3 = x - a3.x, dy3 = y - a3.y;
        float d3 = dx3 * dx3 + dy3 * dy3;
        if (d0 < b0) { b0 = d0; j0 = j;     }
        if (d1 < b1) { b1 = d1; j1 = j + 1; }
        if (d2 < b2) { b2 = d2; j2 = j + 2; }
        if (d3 < b3) { b3 = d3; j3 = j + 3; }
    }
    float best = b0; int bi = j0;
    if (b1 < best || (b1 == best && j1 < bi)) { best = b1; bi = j1; }
    if (b2 < best || (b2 == best && j2 < bi)) { best = b2; bi = j2; }
    if (b3 < best || (b3 == best && j3 < bi)) { best = b3; bi = j3; }
    best_out = best;
    idx_out  = bi;
}

__global__ __launch_bounds__(1024, 1)
void main_kernel(const float* __restrict__ tgt,
                 const float* __restrict__ prd,
                 const float* __restrict__ vis) {
    __shared__ float2 sT[W_UP];
    __shared__ float2 sP[W_UP];
    __shared__ float  sM[W_UP];
    __shared__ int    sIT[W_UP];
    __shared__ int    sIP[W_UP];
    __shared__ float  rM[32], rPn[32], rD[32];

    const int n = blockIdx.x;
    const int i = threadIdx.x;

    const float* t0 = tgt + n * 2 * W_IN;   // channel 0
    const float* t1 = t0 + W_IN;            // channel 1
    const float* p0 = prd + n * 2 * W_IN;
    const float* p1 = p0 + W_IN;
    const float* v0 = vis + n * W_IN;

    // linear interpolation, align_corners=True: pos = i * (W-1)/(W'-1)
    float pos = (float)i * STEP_F;
    int   i0  = (int)pos;                   // pos >= 0 -> trunc == floor
    int   i1  = min(i0 + 1, W_IN - 1);
    float w   = pos - (float)i0;
    float wc  = 1.0f - w;

    float tx = t0[i0] * wc + t0[i1] * w;
    float ty = t1[i0] * wc + t1[i1] * w;
    float px = p0[i0] * wc + p0[i1] * w;
    float py = p1[i0] * wc + p1[i1] * w;
    float m  = v0[i0] * wc + v0[i1] * w;
    if (m < 0.5f) m = 0.0f;

    sT[i] = make_float2(tx, ty);
    sP[i] = make_float2(px, py);
    sM[i] = m;
    __syncthreads();

    // Direction A: _directed_loss(p, t, m) -> for each t_i, min over p_j
    float bT; int iT;
    min_scan(tx, ty, sP, bT, iT);
    // Direction B: _directed_loss(t, p, m) -> for each p_i, min over t_j
    float bP; int iP;
    min_scan(px, py, sT, bP, iP);

    sIT[i] = iT;
    sIP[i] = iP;

    float ddx = tx - px, ddy = ty - py;
    float direct = (ddx * ddx + ddy * ddy) * m;
    float mse    = (bT + bP) * m;
    __syncthreads();

    // index-order penalty: relu(idx[i] - idx[i+1])^2 * m[i]
    float pen = 0.0f;
    if (i < W_UP - 1) {
        float dT = (float)(sIT[i] - sIT[i + 1]);
        float dP = (float)(sIP[i] - sIP[i + 1]);
        float rT = dT > 0.0f ? dT * dT : 0.0f;
        float rP = dP > 0.0f ? dP * dP : 0.0f;
        pen = (rT + rP) * sM[i];
    }

    // block reduction of (mse, pen, direct)
    const unsigned full = 0xffffffffu;
    #pragma unroll
    for (int o = 16; o; o >>= 1) {
        mse    += __shfl_down_sync(full, mse, o);
        pen    += __shfl_down_sync(full, pen, o);
        direct += __shfl_down_sync(full, direct, o);
    }
    int lane = i & 31, wid = i >> 5;
    if (lane == 0) { rM[wid] = mse; rPn[wid] = pen; rD[wid] = direct; }
    __syncthreads();
    if (wid == 0) {
        float a = rM[lane], b = rPn[lane], c = rD[lane];
        #pragma unroll
        for (int o = 16; o; o >>= 1) {
            a += __shfl_down_sync(full, a, o);
            b += __shfl_down_sync(full, b, o);
            c += __shfl_down_sync(full, c, o);
        }
        if (lane == 0) {
            atomicAdd(&g_acc[0], a);
            atomicAdd(&g_acc[1], b);
            atomicAdd(&g_acc[2], c);
        }
    }
}

__global__ void finalize_kernel(float* __restrict__ out) {
    const float cnt_mse = (float)(N_BATCH * W_UP);        // 131072
    const float cnt_pen = (float)(N_BATCH * (W_UP - 1));  // 130944
    float mse_mean = g_acc[0] / cnt_mse;   // (meanA + meanB)
    float pen_mean = g_acc[1] / cnt_pen;   // (penA_mean + penB_mean)
    float matched  = 0.5f * mse_mean + 0.5f * 0.1f * pen_mean;
    float direct   = g_acc[2] / cnt_mse;
    out[0] = fminf(matched, direct);
}

extern "C" void kernel_launch(void* const* d_in, const int* in_sizes, int n_in,
                              void* d_out, int out_size) {
    (void)in_sizes; (void)n_in; (void)out_size;
    const float* tgt = (const float*)d_in[0];
    const float* prd = (const float*)d_in[1];
    const float* vis = (const float*)d_in[2];

    zero_kernel<<<1, 32>>>();
    main_kernel<<<N_BATCH, W_UP>>>(tgt, prd, vis);
    finalize_kernel<<<1, 1>>>((float*)d_out);
}

// round 7
// speedup vs baseline: 1.3320x; 1.3320x over previous
#include <cuda_runtime.h>
#include <math_constants.h>

#define N_BATCH 128
#define W_IN    128
#define W_UP    1024
#define STEP_F  (127.0f / 1023.0f)
#define SPLIT   8
#define BLK     128

// Accumulators: [0] = sum (min-dist * mask) both directions,
//               [1] = sum index-order penalties both directions,
//               [2] = sum direct squared error * mask.
__device__ float g_acc[3];
// Argmin indices: gIT = argmin over p for each t-point, gIP = argmin over t for each p-point.
__device__ int gIT[N_BATCH * W_UP];
__device__ int gIP[N_BATCH * W_UP];

__global__ void zero_kernel() {
    if (threadIdx.x < 3) g_acc[threadIdx.x] = 0.0f;
}

// Min of c_j = nb[j] - 2x*ax[j] - 2y*ay[j] over j=0..1023 (value via packed f32x2 FFMA +
// scalar min chain; no per-candidate index tracking), then exact argmin by rescanning the
// winning 32-candidate segment with bitwise-identical scalar FFMAs. Ties resolved to the
// smallest index (matches jnp.argmin first-occurrence).
__device__ __forceinline__ void scan_min(const float* __restrict__ ax,
                                         const float* __restrict__ ay,
                                         const float* __restrict__ nb,
                                         float x, float y, int lane,
                                         float& best_out, int& idx_out) {
    float X = -2.0f * x, Y = -2.0f * y;
    unsigned long long Xp, Yp;
    asm("mov.b64 %0, {%1, %1};" : "=l"(Xp) : "f"(X));
    asm("mov.b64 %0, {%1, %1};" : "=l"(Yp) : "f"(Y));

    float best = CUDART_INF_F;
    int bseg = 0;
    for (int s = 0; s < 32; s++) {          // 32 segments x 32 candidates
        float b0 = CUDART_INF_F, b1 = CUDART_INF_F;
        const int base = s * 32;
        #pragma unroll
        for (int g = 0; g < 8; g++) {       // 4 candidates per group
            const int j = base + g * 4;
            ulonglong2 axq = *(const ulonglong2*)(ax + j);  // (ax[j],ax[j+1]) , (ax[j+2],ax[j+3])
            ulonglong2 ayq = *(const ulonglong2*)(ay + j);
            ulonglong2 nbq = *(const ulonglong2*)(nb + j);
            asm("{\n\t"
                ".reg .b64 t;\n\t.reg .f32 lo, hi;\n\t"
                "fma.rn.f32x2 t, %2, %3, %4;\n\t"
                "fma.rn.f32x2 t, %5, %6, t;\n\t"
                "mov.b64 {lo, hi}, t;\n\t"
                "min.f32 %0, %0, lo;\n\t"
                "min.f32 %1, %1, hi;\n\t"
                "}"
                : "+f"(b0), "+f"(b1)
                : "l"(Yp), "l"(ayq.x), "l"(nbq.x), "l"(Xp), "l"(axq.x));
            asm("{\n\t"
                ".reg .b64 t;\n\t.reg .f32 lo, hi;\n\t"
                "fma.rn.f32x2 t, %2, %3, %4;\n\t"
                "fma.rn.f32x2 t, %5, %6, t;\n\t"
                "mov.b64 {lo, hi}, t;\n\t"
                "min.f32 %0, %0, lo;\n\t"
                "min.f32 %1, %1, hi;\n\t"
                "}"
                : "+f"(b0), "+f"(b1)
                : "l"(Yp), "l"(ayq.y), "l"(nbq.y), "l"(Xp), "l"(axq.y));
        }
        float bs = fminf(b0, b1);
        if (bs < best) { best = bs; bseg = s; }   // strict < keeps first segment on ties
    }

    // Rescan winning segment. Lane-rotated index so lanes with different segments hit
    // distinct banks (addr mod 32 = (k+lane)&31, distinct per lane).
    const int base = bseg * 32;
    int idx = 0x3fffffff;
    #pragma unroll 4
    for (int k = 0; k < 32; k++) {
        int j = (k + lane) & 31;
        float c = fmaf(X, ax[base + j], fmaf(Y, ay[base + j], nb[base + j]));
        if (c == best) idx = min(idx, base + j);  // exact bitwise match guaranteed
    }
    best_out = best;
    idx_out = idx;
}

__global__ __launch_bounds__(BLK, 8)
void main_kernel(const float* __restrict__ tgt,
                 const float* __restrict__ prd,
                 const float* __restrict__ vis) {
    __shared__ __align__(16) float sTx[W_UP];
    __shared__ __align__(16) float sTy[W_UP];
    __shared__ __align__(16) float sPx[W_UP];
    __shared__ __align__(16) float sPy[W_UP];
    __shared__ __align__(16) float sTnb[W_UP];
    __shared__ __align__(16) float sPnb[W_UP];
    __shared__ float red[3][4];

    const int n    = blockIdx.x >> 3;
    const int qseg = blockIdx.x & (SPLIT - 1);
    const int tid  = threadIdx.x;
    const int lane = tid & 31;
    const int wid  = tid >> 5;

    const float* t0 = tgt + n * 2 * W_IN;
    const float* t1 = t0 + W_IN;
    const float* p0 = prd + n * 2 * W_IN;
    const float* p1 = p0 + W_IN;
    const float* v0 = vis + n * W_IN;

    float qtx = 0.f, qty = 0.f, qpx = 0.f, qpy = 0.f, qm = 0.f;

    #pragma unroll
    for (int r = 0; r < SPLIT; r++) {
        int i = r * BLK + tid;
        float pos = (float)i * STEP_F;
        int   i0  = (int)pos;
        int   i1  = min(i0 + 1, W_IN - 1);
        float w   = pos - (float)i0;
        float wc  = 1.0f - w;

        float tx = t0[i0] * wc + t0[i1] * w;
        float ty = t1[i0] * wc + t1[i1] * w;
        float px = p0[i0] * wc + p0[i1] * w;
        float py = p1[i0] * wc + p1[i1] * w;
        float m  = v0[i0] * wc + v0[i1] * w;
        if (m < 0.5f) m = 0.0f;

        sTx[i] = tx; sTy[i] = ty;
        sPx[i] = px; sPy[i] = py;
        sTnb[i] = tx * tx + ty * ty;
        sPnb[i] = px * px + py * py;
        if (r == qseg) { qtx = tx; qty = ty; qpx = px; qpy = py; qm = m; }
    }
    __syncthreads();

    const int q = qseg * BLK + tid;

    float bA; int iA;   // t-query vs p-candidates  (_directed_loss(p, t))
    scan_min(sPx, sPy, sPnb, qtx, qty, lane, bA, iA);
    float bB; int iB;   // p-query vs t-candidates  (_directed_loss(t, p))
    scan_min(sTx, sTy, sTnb, qpx, qpy, lane, bB, iB);

    gIT[n * W_UP + q] = iA;
    gIP[n * W_UP + q] = iB;

    float dA = bA + (qtx * qtx + qty * qty);
    float dB = bB + (qpx * qpx + qpy * qpy);
    float mse = (dA + dB) * qm;

    float ddx = qtx - qpx, ddy = qty - qpy;
    float direct = (ddx * ddx + ddy * ddy) * qm;

    const unsigned full = 0xffffffffu;
    #pragma unroll
    for (int o = 16; o; o >>= 1) {
        mse    += __shfl_down_sync(full, mse, o);
        direct += __shfl_down_sync(full, direct, o);
    }
    if (lane == 0) { red[0][wid] = mse; red[1][wid] = direct; }
    __syncthreads();
    if (tid == 0) {
        float a = red[0][0] + red[0][1] + red[0][2] + red[0][3];
        float c = red[1][0] + red[1][1] + red[1][2] + red[1][3];
        atomicAdd(&g_acc[0], a);
        atomicAdd(&g_acc[2], c);
    }
}

__global__ __launch_bounds__(1024)
void pen_kernel(const float* __restrict__ vis) {
    __shared__ float red[32];
    const int n = blockIdx.x;
    const int i = threadIdx.x;
    const float* v0 = vis + n * W_IN;

    float pen = 0.0f;
    if (i < W_UP - 1) {
        float pos = (float)i * STEP_F;
        int   i0  = (int)pos;
        int   i1  = min(i0 + 1, W_IN - 1);
        float w   = pos - (float)i0;
        float m   = v0[i0] * (1.0f - w) + v0[i1] * w;
        if (m < 0.5f) m = 0.0f;

        int a0 = gIT[n * W_UP + i], a1 = gIT[n * W_UP + i + 1];
        int b0 = gIP[n * W_UP + i], b1 = gIP[n * W_UP + i + 1];
        float dT = (float)(a0 - a1);
        float dP = (float)(b0 - b1);
        float rT = dT > 0.0f ? dT * dT : 0.0f;
        float rP = dP > 0.0f ? dP * dP : 0.0f;
        pen = (rT + rP) * m;
    }

    const unsigned full = 0xffffffffu;
    #pragma unroll
    for (int o = 16; o; o >>= 1) pen += __shfl_down_sync(full, pen, o);
    int lane = i & 31, wid = i >> 5;
    if (lane == 0) red[wid] = pen;
    __syncthreads();
    if (wid == 0) {
        float a = red[lane];
        #pragma unroll
        for (int o = 16; o; o >>= 1) a += __shfl_down_sync(full, a, o);
        if (lane == 0) atomicAdd(&g_acc[1], a);
    }
}

__global__ void finalize_kernel(float* __restrict__ out) {
    const float cnt_mse = (float)(N_BATCH * W_UP);        // 131072
    const float cnt_pen = (float)(N_BATCH * (W_UP - 1));  // 130944
    float mse_mean = g_acc[0] / cnt_mse;
    float pen_mean = g_acc[1] / cnt_pen;
    float matched  = 0.5f * mse_mean + 0.5f * 0.1f * pen_mean;
    float direct   = g_acc[2] / cnt_mse;
    out[0] = fminf(matched, direct);
}

extern "C" void kernel_launch(void* const* d_in, const int* in_sizes, int n_in,
                              void* d_out, int out_size) {
    (void)in_sizes; (void)n_in; (void)out_size;
    const float* tgt = (const float*)d_in[0];
    const float* prd = (const float*)d_in[1];
    const float* vis = (const float*)d_in[2];

    zero_kernel<<<1, 32>>>();
    main_kernel<<<N_BATCH * SPLIT, BLK>>>(tgt, prd, vis);
    pen_kernel<<<N_BATCH, 1024>>>(vis);
    finalize_kernel<<<1, 1>>>((float*)d_out);
}

// round 8
// speedup vs baseline: 2.0782x; 1.5602x over previous
#include <cuda_runtime.h>
#include <math_constants.h>

#define N_BATCH 128
#define W_IN    128
#define W_UP    1024
#define STEP_F  (127.0f / 1023.0f)
#define BLK     128
#define NBLOCKS (N_BATCH * 8)   // n * {dir:2} * {chunk:4}, 256 queries per block

// Per-block partials (no atomics, no zeroing kernel needed).
__device__ float gMse[NBLOCKS];
__device__ float gPen[NBLOCKS];
__device__ float gDir[NBLOCKS];
// First/last argmin index of each block's 256-query chunk (for boundary penalty pairs).
__device__ int gFirst[NBLOCKS];
__device__ int gLast[NBLOCKS];

// packed 2-candidate step: c = nb - 2x*ax - 2y*ay via two chained fma.rn.f32x2,
// then scalar mins into the lo/hi accumulators. mov.b64 {lo,hi} is register
// aliasing (no SASS MOV expected).
#define PACKMIN(b0, b1, Yp, ayp, nbp, Xp, axp)                \
    asm("{\n\t"                                               \
        ".reg .b64 t;\n\t.reg .f32 lo, hi;\n\t"               \
        "fma.rn.f32x2 t, %2, %3, %4;\n\t"                     \
        "fma.rn.f32x2 t, %5, %6, t;\n\t"                      \
        "mov.b64 {lo, hi}, t;\n\t"                            \
        "min.f32 %0, %0, lo;\n\t"                             \
        "min.f32 %1, %1, hi;\n\t"                             \
        "}" : "+f"(b0), "+f"(b1)                              \
        : "l"(Yp), "l"(ayp), "l"(nbp), "l"(Xp), "l"(axp))

// Exact argmin inside the winning 32-candidate segment: scalar FFMAs are
// bitwise-identical to the packed lanes; ties -> smallest index (jnp.argmin).
// Lane-rotated index avoids 32-way bank conflicts when lanes diverge on seg.
__device__ __forceinline__ int rescan(const float* __restrict__ ax,
                                      const float* __restrict__ ay,
                                      const float* __restrict__ nb,
                                      float X, float Y, int seg, float best,
                                      int lane) {
    const int base = seg * 32;
    int idx = 0x3fffffff;
    #pragma unroll 4
    for (int k = 0; k < 32; k++) {
        int j = (k + lane) & 31;
        float c = fmaf(X, ax[base + j], fmaf(Y, ay[base + j], nb[base + j]));
        if (c == best) idx = min(idx, base + j);
    }
    return idx;
}

// Min+argmin over 1024 candidates for TWO queries (register-blocked: each
// candidate group is loaded once from smem and used by both queries).
__device__ __forceinline__ void scan2(const float* __restrict__ ax,
                                      const float* __restrict__ ay,
                                      const float* __restrict__ nb,
                                      float x0, float y0, float x1, float y1,
                                      int lane,
                                      float& bo0, int& io0,
                                      float& bo1, int& io1) {
    float X0 = -2.0f * x0, Y0 = -2.0f * y0;
    float X1 = -2.0f * x1, Y1 = -2.0f * y1;
    unsigned long long X0p, Y0p, X1p, Y1p;
    asm("mov.b64 %0, {%1, %1};" : "=l"(X0p) : "f"(X0));
    asm("mov.b64 %0, {%1, %1};" : "=l"(Y0p) : "f"(Y0));
    asm("mov.b64 %0, {%1, %1};" : "=l"(X1p) : "f"(X1));
    asm("mov.b64 %0, {%1, %1};" : "=l"(Y1p) : "f"(Y1));

    float best0 = CUDART_INF_F, best1 = CUDART_INF_F;
    int seg0 = 0, seg1 = 0;
    for (int s = 0; s < 32; s++) {
        float a0 = CUDART_INF_F, a1 = CUDART_INF_F;   // q0: even/odd chains
        float c0 = CUDART_INF_F, c1 = CUDART_INF_F;   // q1
        const int sb = s * 32;
        #pragma unroll
        for (int g = 0; g < 8; g++) {
            const int j = sb + g * 4;
            ulonglong2 axq = *(const ulonglong2*)(ax + j);
            ulonglong2 ayq = *(const ulonglong2*)(ay + j);
            ulonglong2 nbq = *(const ulonglong2*)(nb + j);
            PACKMIN(a0, a1, Y0p, ayq.x, nbq.x, X0p, axq.x);
            PACKMIN(a0, a1, Y0p, ayq.y, nbq.y, X0p, axq.y);
            PACKMIN(c0, c1, Y1p, ayq.x, nbq.x, X1p, axq.x);
            PACKMIN(c0, c1, Y1p, ayq.y, nbq.y, X1p, axq.y);
        }
        float m0 = fminf(a0, a1);
        if (m0 < best0) { best0 = m0; seg0 = s; }   // strict < keeps first seg on ties
        float m1 = fminf(c0, c1);
        if (m1 < best1) { best1 = m1; seg1 = s; }
    }
    io0 = rescan(ax, ay, nb, X0, Y0, seg0, best0, lane);
    io1 = rescan(ax, ay, nb, X1, Y1, seg1, best1, lane);
    bo0 = best0;
    bo1 = best1;
}

__global__ __launch_bounds__(BLK, 8)
void main_kernel(const float* __restrict__ tgt,
                 const float* __restrict__ prd,
                 const float* __restrict__ vis) {
    __shared__ __align__(16) float sAx[W_UP];
    __shared__ __align__(16) float sAy[W_UP];
    __shared__ __align__(16) float sAnb[W_UP];
    __shared__ int   sIdx[256];
    __shared__ float sM[256];
    __shared__ float red[3][4];

    const int b     = blockIdx.x;
    const int n     = b >> 3;
    const int dir   = (b >> 2) & 1;   // 0: queries=t, candidates=p; 1: swapped
    const int chunk = b & 3;          // 256-query chunk
    const int tid   = threadIdx.x;
    const int lane  = tid & 31;
    const int wid   = tid >> 5;

    const float* t0 = tgt + n * 2 * W_IN;
    const float* t1 = t0 + W_IN;
    const float* p0 = prd + n * 2 * W_IN;
    const float* p1 = p0 + W_IN;
    const float* v0 = vis + n * W_IN;

    // query 0 = chunk*256 + tid, query 1 = chunk*256 + 128 + tid
    float q0x = 0.f, q0y = 0.f, q0m = 0.f, dir0 = 0.f;
    float q1x = 0.f, q1y = 0.f, q1m = 0.f, dir1 = 0.f;

    #pragma unroll
    for (int r = 0; r < 8; r++) {
        int i = r * BLK + tid;
        float pos = (float)i * STEP_F;
        int   i0  = (int)pos;
        int   i1  = min(i0 + 1, W_IN - 1);
        float w   = pos - (float)i0;
        float wc  = 1.0f - w;

        float tx = t0[i0] * wc + t0[i1] * w;
        float ty = t1[i0] * wc + t1[i1] * w;
        float px = p0[i0] * wc + p0[i1] * w;
        float py = p1[i0] * wc + p1[i1] * w;
        float m  = v0[i0] * wc + v0[i1] * w;
        if (m < 0.5f) m = 0.0f;

        float cx = dir ? tx : px;     // candidates = opposite array
        float cy = dir ? ty : py;
        sAx[i]  = cx;
        sAy[i]  = cy;
        sAnb[i] = cx * cx + cy * cy;

        if (r == 2 * chunk) {
            q0x = dir ? px : tx; q0y = dir ? py : ty; q0m = m;
            float ddx = tx - px, ddy = ty - py;
            dir0 = (ddx * ddx + ddy * ddy) * m;
        }
        if (r == 2 * chunk + 1) {
            q1x = dir ? px : tx; q1y = dir ? py : ty; q1m = m;
            float ddx = tx - px, ddy = ty - py;
            dir1 = (ddx * ddx + ddy * ddy) * m;
        }
    }
    __syncthreads();

    float b0, b1; int i0a, i1a;
    scan2(sAx, sAy, sAnb, q0x, q0y, q1x, q1y, lane, b0, i0a, b1, i1a);

    float mse = (b0 + (q0x * q0x + q0y * q0y)) * q0m
              + (b1 + (q1x * q1x + q1y * q1y)) * q1m;
    // direct error counted once (dir==0 blocks cover all queries)
    float direct = dir ? 0.0f : (dir0 + dir1);

    sIdx[tid]       = i0a;
    sIdx[128 + tid] = i1a;
    sM[tid]         = q0m;
    sM[128 + tid]   = q1m;
    __syncthreads();

    // internal index-order penalty: 255 pairs inside this chunk
    float pen = 0.0f;
    for (int li = tid; li < 255; li += BLK) {
        float d = (float)(sIdx[li] - sIdx[li + 1]);
        float r = d > 0.0f ? d * d : 0.0f;
        pen += r * sM[li];
    }
    if (tid == 0) { gFirst[b] = sIdx[0]; gLast[b] = sIdx[255]; }

    const unsigned full = 0xffffffffu;
    #pragma unroll
    for (int o = 16; o; o >>= 1) {
        mse    += __shfl_down_sync(full, mse, o);
        pen    += __shfl_down_sync(full, pen, o);
        direct += __shfl_down_sync(full, direct, o);
    }
    if (lane == 0) { red[0][wid] = mse; red[1][wid] = pen; red[2][wid] = direct; }
    __syncthreads();
    if (tid == 0) {
        gMse[b] = red[0][0] + red[0][1] + red[0][2] + red[0][3];
        gPen[b] = red[1][0] + red[1][1] + red[1][2] + red[1][3];
        gDir[b] = red[2][0] + red[2][1] + red[2][2] + red[2][3];
    }
}

__global__ __launch_bounds__(1024)
void finalize_kernel(const float* __restrict__ vis, float* __restrict__ out) {
    __shared__ float red[3][32];
    const int tid  = threadIdx.x;
    const int lane = tid & 31;
    const int wid  = tid >> 5;

    float mse = gMse[tid];
    float pen = gPen[tid];
    float dct = gDir[tid];

    // 768 boundary penalty pairs: (n, dir, boundary 0..2) between chunks
    if (tid < N_BATCH * 2 * 3) {
        int n   = tid / 6;
        int rem = tid % 6;
        int dir = rem / 3;
        int bd  = rem % 3;
        int lb  = n * 8 + dir * 4 + bd;     // left chunk's block id
        int i   = bd * 256 + 255;           // global pair index
        float pos = (float)i * STEP_F;
        int   i0  = (int)pos;
        int   i1  = min(i0 + 1, W_IN - 1);
        float w   = pos - (float)i0;
        float m   = vis[n * W_IN + i0] * (1.0f - w) + vis[n * W_IN + i1] * w;
        if (m < 0.5f) m = 0.0f;
        float d = (float)(gLast[lb] - gFirst[lb + 1]);
        float r = d > 0.0f ? d * d : 0.0f;
        pen += r * m;
    }

    const unsigned full = 0xffffffffu;
    #pragma unroll
    for (int o = 16; o; o >>= 1) {
        mse += __shfl_down_sync(full, mse, o);
        pen += __shfl_down_sync(full, pen, o);
        dct += __shfl_down_sync(full, dct, o);
    }
    if (lane == 0) { red[0][wid] = mse; red[1][wid] = pen; red[2][wid] = dct; }
    __syncthreads();
    if (wid == 0) {
        float a = red[0][lane], c = red[1][lane], e = red[2][lane];
        #pragma unroll
        for (int o = 16; o; o >>= 1) {
            a += __shfl_down_sync(full, a, o);
            c += __shfl_down_sync(full, c, o);
            e += __shfl_down_sync(full, e, o);
        }
        if (lane == 0) {
            const float cnt_mse = (float)(N_BATCH * W_UP);        // 131072
            const float cnt_pen = (float)(N_BATCH * (W_UP - 1));  // 130944
            float mse_mean = a / cnt_mse;      // meanA + meanB
            float pen_mean = c / cnt_pen;      // penA_mean + penB_mean
            float matched  = 0.5f * mse_mean + 0.5f * 0.1f * pen_mean;
            float direct   = e / cnt_mse;
            out[0] = fminf(matched, direct);
        }
    }
}

extern "C" void kernel_launch(void* const* d_in, const int* in_sizes, int n_in,
                              void* d_out, int out_size) {
    (void)in_sizes; (void)n_in; (void)out_size;
    const float* tgt = (const float*)d_in[0];
    const float* prd = (const float*)d_in[1];
    const float* vis = (const float*)d_in[2];

    main_kernel<<<NBLOCKS, BLK>>>(tgt, prd, vis);
    finalize_kernel<<<1, 1024>>>(vis, (float*)d_out);
}